// round 13
// baseline (speedup 1.0000x reference)
#include <cuda_runtime.h>
#include <cuda_fp16.h>

#define N_CELLS 50000
#define N_EDGES 1600000
#define D_IN 256
#define D_OUT 128
#define MAXD 128

// ---- scratch (device globals; no allocation allowed) ----
__device__ float  g_m[N_CELLS * D_OUT];     // x @ W fp32 (frozen numerics; feeds scores)
__device__ __half g_mh[N_CELLS * D_OUT];    // fp16 copy (feeds agg numerator)
__device__ float  g_ssrc[N_CELLS];
__device__ float  g_sdst[N_CELLS];
__device__ int    g_cnt[N_CELLS];           // zeroed by agg at end of each run
__device__ int    g_rowstart[N_CELLS];
__device__ int    g_fill[N_CELLS];
__device__ int    g_total;
__device__ int2   g_pairs[N_EDGES];         // (dst, float_bits(n_val)) grouped by src

// ---- packed f32x2 helpers (FFMA2: each half IEEE fp32 RN, bit == scalar fmaf) ----
__device__ __forceinline__ unsigned long long pk2(float lo, float hi) {
    unsigned long long r;
    asm("mov.b64 %0, {%1, %2};" : "=l"(r) : "f"(lo), "f"(hi));
    return r;
}
__device__ __forceinline__ void upk2(unsigned long long v, float& lo, float& hi) {
    asm("mov.b64 {%0, %1}, %2;" : "=f"(lo), "=f"(hi) : "l"(v));
}
__device__ __forceinline__ unsigned long long ffma2(unsigned long long a,
                                                    unsigned long long b,
                                                    unsigned long long c) {
    unsigned long long d;
    asm("fma.rn.f32x2 %0, %1, %2, %3;" : "=l"(d) : "l"(a), "l"(b), "l"(c));
    return d;
}

// ================= GEMM: g_m = x @ W (dup-B smem, FFMA2, frozen k-order) =================
#define BM 128
#define BK 16

__global__ __launch_bounds__(256) void gemm_kernel(const float* __restrict__ x,
                                                   const float* __restrict__ W) {
    __shared__ float As[BK][BM + 4];
    __shared__ float BsD[BK][256];   // duplicated B: logical word w=2j holds B[k][j] twice
    const int tid = threadIdx.x;
    const int blockRow = blockIdx.x * BM;
    const int tx = tid & 15;
    const int ty = tid >> 4;

    // acc2[rp][c]: rows (2rp, 2rp+1) of this thread's 8 rows, col c of 8
    unsigned long long acc2[4][8];
#pragma unroll
    for (int rp = 0; rp < 4; rp++)
#pragma unroll
        for (int c = 0; c < 8; c++) acc2[rp][c] = 0ull;

    const int rowA = tid >> 2;          // 0..63
    const int colA = (tid & 3) << 2;    // 0,4,8,12
    const int rowB = tid >> 5;          // 0..7
    const int colB = (tid & 31) << 2;   // 0..124
    const int wB = colB * 2;                         // logical dup-word base (8-aligned)
    const int swSt = ((wB >> 5) & 3) << 2;           // store-side swizzle (bits 2-3)
    const int swR = ((tx >> 1) & 3) << 2;            // read-side swizzle

    const int grA0 = blockRow + rowA;
    const int grA1 = blockRow + rowA + 64;
    const bool okA0 = grA0 < N_CELLS;
    const bool okA1 = grA1 < N_CELLS;
    const float* pA0 = x + (size_t)(okA0 ? grA0 : 0) * D_IN + colA;
    const float* pA1 = x + (size_t)(okA1 ? grA1 : 0) * D_IN + colA;
    const float* pB0 = W + (size_t)rowB * D_OUT + colB;
    const float* pB1 = W + (size_t)(rowB + 8) * D_OUT + colB;

    // prologue: tile kk=0 into smem
    {
        float4 a0 = okA0 ? *(const float4*)pA0 : make_float4(0.f, 0.f, 0.f, 0.f);
        float4 a1 = okA1 ? *(const float4*)pA1 : make_float4(0.f, 0.f, 0.f, 0.f);
        float4 b0 = *(const float4*)pB0;
        float4 b1 = *(const float4*)pB1;
        As[colA + 0][rowA] = a0.x; As[colA + 1][rowA] = a0.y;
        As[colA + 2][rowA] = a0.z; As[colA + 3][rowA] = a0.w;
        As[colA + 0][rowA + 64] = a1.x; As[colA + 1][rowA + 64] = a1.y;
        As[colA + 2][rowA + 64] = a1.z; As[colA + 3][rowA + 64] = a1.w;
        *(float4*)&BsD[rowB][wB ^ swSt]       = make_float4(b0.x, b0.x, b0.y, b0.y);
        *(float4*)&BsD[rowB][(wB + 4) ^ swSt] = make_float4(b0.z, b0.z, b0.w, b0.w);
        *(float4*)&BsD[rowB + 8][wB ^ swSt]       = make_float4(b1.x, b1.x, b1.y, b1.y);
        *(float4*)&BsD[rowB + 8][(wB + 4) ^ swSt] = make_float4(b1.z, b1.z, b1.w, b1.w);
    }
    __syncthreads();

    for (int kk = 0; kk < D_IN; kk += BK) {
        float4 na0, na1, nb0, nb1;
        const bool more = (kk + BK) < D_IN;
        if (more) {
            na0 = okA0 ? *(const float4*)(pA0 + kk + BK) : make_float4(0.f, 0.f, 0.f, 0.f);
            na1 = okA1 ? *(const float4*)(pA1 + kk + BK) : make_float4(0.f, 0.f, 0.f, 0.f);
            nb0 = *(const float4*)(pB0 + (size_t)(kk + BK) * D_OUT);
            nb1 = *(const float4*)(pB1 + (size_t)(kk + BK) * D_OUT);
        }
#pragma unroll
        for (int k = 0; k < BK; k++) {
            float4 a0 = *(const float4*)(&As[k][ty * 8]);
            float4 a1 = *(const float4*)(&As[k][ty * 8 + 4]);
            const float* bd = &BsD[k][tx * 16];
            float4 q0 = *(const float4*)(bd + (0 ^ swR));
            float4 q1 = *(const float4*)(bd + (4 ^ swR));
            float4 q2 = *(const float4*)(bd + (8 ^ swR));
            float4 q3 = *(const float4*)(bd + (12 ^ swR));
            // row pairs (free: consecutive regs) and dup col pairs (free from memory)
            unsigned long long ap[4] = {pk2(a0.x, a0.y), pk2(a0.z, a0.w),
                                        pk2(a1.x, a1.y), pk2(a1.z, a1.w)};
            unsigned long long bp[8] = {pk2(q0.x, q0.y), pk2(q0.z, q0.w),
                                        pk2(q1.x, q1.y), pk2(q1.z, q1.w),
                                        pk2(q2.x, q2.y), pk2(q2.z, q2.w),
                                        pk2(q3.x, q3.y), pk2(q3.z, q3.w)};
#pragma unroll
            for (int rp = 0; rp < 4; rp++)
#pragma unroll
                for (int c = 0; c < 8; c++)
                    acc2[rp][c] = ffma2(ap[rp], bp[c], acc2[rp][c]);
        }
        __syncthreads();
        if (more) {
            As[colA + 0][rowA] = na0.x; As[colA + 1][rowA] = na0.y;
            As[colA + 2][rowA] = na0.z; As[colA + 3][rowA] = na0.w;
            As[colA + 0][rowA + 64] = na1.x; As[colA + 1][rowA + 64] = na1.y;
            As[colA + 2][rowA + 64] = na1.z; As[colA + 3][rowA + 64] = na1.w;
            *(float4*)&BsD[rowB][wB ^ swSt]       = make_float4(nb0.x, nb0.x, nb0.y, nb0.y);
            *(float4*)&BsD[rowB][(wB + 4) ^ swSt] = make_float4(nb0.z, nb0.z, nb0.w, nb0.w);
            *(float4*)&BsD[rowB + 8][wB ^ swSt]       = make_float4(nb1.x, nb1.x, nb1.y, nb1.y);
            *(float4*)&BsD[rowB + 8][(wB + 4) ^ swSt] = make_float4(nb1.z, nb1.z, nb1.w, nb1.w);
            __syncthreads();
        }
    }

#pragma unroll
    for (int r = 0; r < 8; r++) {
        int gr = blockRow + ty * 8 + r;
        if (gr < N_CELLS) {
            float f[8];
#pragma unroll
            for (int c = 0; c < 8; c++) {
                float lo, hi;
                upk2(acc2[r >> 1][c], lo, hi);
                f[c] = (r & 1) ? hi : lo;
            }
            float* dst = g_m + (size_t)gr * D_OUT + tx * 8;
            *(float4*)dst = make_float4(f[0], f[1], f[2], f[3]);
            *(float4*)(dst + 4) = make_float4(f[4], f[5], f[6], f[7]);
            __half2 h0 = __floats2half2_rn(f[0], f[1]);
            __half2 h1 = __floats2half2_rn(f[2], f[3]);
            __half2 h2 = __floats2half2_rn(f[4], f[5]);
            __half2 h3 = __floats2half2_rn(f[6], f[7]);
            uint4 hv;
            hv.x = *(unsigned int*)&h0;
            hv.y = *(unsigned int*)&h1;
            hv.z = *(unsigned int*)&h2;
            hv.w = *(unsigned int*)&h3;
            *(uint4*)(g_mh + (size_t)gr * D_OUT + tx * 8) = hv;
        }
    }
}

// ================= scores: cublas-gemv emulation (FROZEN numerics) =================
__global__ __launch_bounds__(256) void score_kernel(const float* __restrict__ a) {
    __shared__ float sa[2 * D_OUT];
    for (int j = threadIdx.x; j < 2 * D_OUT; j += blockDim.x) sa[j] = a[j];
    __syncthreads();
    int row = (blockIdx.x * blockDim.x + threadIdx.x) >> 5;
    int l = threadIdx.x & 31;
    if (row >= N_CELLS) return;
    const float* __restrict__ mr = g_m + (size_t)row * D_OUT;

    float m0 = __ldg(mr + l);
    float m1 = __ldg(mr + l + 32);
    float m2 = __ldg(mr + l + 64);
    float m3 = __ldg(mr + l + 96);

    float ss = fmaf(m0, sa[l], 0.f);
    ss = fmaf(m1, sa[l + 32], ss);
    ss = fmaf(m2, sa[l + 64], ss);
    ss = fmaf(m3, sa[l + 96], ss);

    float sd = fmaf(m0, sa[D_OUT + l], 0.f);
    sd = fmaf(m1, sa[D_OUT + l + 32], sd);
    sd = fmaf(m2, sa[D_OUT + l + 64], sd);
    sd = fmaf(m3, sa[D_OUT + l + 96], sd);

#pragma unroll
    for (int off = 16; off > 0; off >>= 1) {
        ss += __shfl_down_sync(0xffffffffu, ss, off);
        sd += __shfl_down_sync(0xffffffffu, sd, off);
    }
    if (l == 0) {
        g_ssrc[row] = ss;
        g_sdst[row] = sd;
    }
}

// ================= CSR build (scan-free) =================
__global__ void hist_kernel(const int* __restrict__ n_src) {
    if (blockIdx.x == 0 && threadIdx.x == 0) g_total = 0;
    int e = (blockIdx.x * blockDim.x + threadIdx.x) * 8;
    if (e < N_EDGES) {
        int4 s0 = *(const int4*)(n_src + e);
        int4 s1 = *(const int4*)(n_src + e + 4);
        atomicAdd(&g_cnt[s0.x], 1);
        atomicAdd(&g_cnt[s0.y], 1);
        atomicAdd(&g_cnt[s0.z], 1);
        atomicAdd(&g_cnt[s0.w], 1);
        atomicAdd(&g_cnt[s1.x], 1);
        atomicAdd(&g_cnt[s1.y], 1);
        atomicAdd(&g_cnt[s1.z], 1);
        atomicAdd(&g_cnt[s1.w], 1);
    }
}

__global__ __launch_bounds__(256) void alloc_kernel() {
    int i = blockIdx.x * blockDim.x + threadIdx.x;
    int lane = threadIdx.x & 31;
    int cnt = (i < N_CELLS) ? g_cnt[i] : 0;
    int xv = cnt;
#pragma unroll
    for (int off = 1; off < 32; off <<= 1) {
        int y = __shfl_up_sync(0xffffffffu, xv, off);
        if (lane >= off) xv += y;
    }
    int excl = xv - cnt;
    int wtotal = __shfl_sync(0xffffffffu, xv, 31);
    int base = 0;
    if (lane == 0) base = atomicAdd(&g_total, wtotal);
    base = __shfl_sync(0xffffffffu, base, 0);
    if (i < N_CELLS) {
        int s = base + excl;
        g_rowstart[i] = s;
        g_fill[i] = s;
    }
}

__global__ void scatter_kernel(const int* __restrict__ n_src,
                               const int* __restrict__ n_dst,
                               const float* __restrict__ n_vals) {
    int e = (blockIdx.x * blockDim.x + threadIdx.x) * 4;
    if (e < N_EDGES) {
        int4 s = *(const int4*)(n_src + e);
        int4 d = *(const int4*)(n_dst + e);
        float4 v = *(const float4*)(n_vals + e);
        int p0 = atomicAdd(&g_fill[s.x], 1);
        int p1 = atomicAdd(&g_fill[s.y], 1);
        int p2 = atomicAdd(&g_fill[s.z], 1);
        int p3 = atomicAdd(&g_fill[s.w], 1);
        g_pairs[p0] = make_int2(d.x, __float_as_int(v.x));
        g_pairs[p1] = make_int2(d.y, __float_as_int(v.y));
        g_pairs[p2] = make_int2(d.z, __float_as_int(v.z));
        g_pairs[p3] = make_int2(d.w, __float_as_int(v.w));
    }
}

// ================= aggregation (denominator FROZEN; numerator fp16 m) =================
__global__ __launch_bounds__(256) void agg_kernel(float* __restrict__ out) {
    __shared__ float ebuf[8][MAXD];
    const int w = threadIdx.x >> 5;
    int i = (blockIdx.x * blockDim.x + threadIdx.x) >> 5;
    int lane = threadIdx.x & 31;
    if (i >= N_CELLS) return;
    int start = g_rowstart[i];
    int d = g_cnt[i];
    if (lane == 0) g_cnt[i] = 0;    // reset for next run (replaces zero_kernel)
    int end = start + d;
    float si = g_ssrc[i];

    // pass 1: e values (cached in smem) + fp64 rs
    double rsd = 0.0;
    for (int j = start + lane; j < end; j += 32) {
        int dst = g_pairs[j].x;
        float z = si + g_sdst[dst];
        float e = z >= 0.f ? z : 0.2f * z;
        int t = j - start;
        if (t < MAXD) ebuf[w][t] = e;
        rsd += (double)e;
    }
#pragma unroll
    for (int off = 16; off > 0; off >>= 1)
        rsd += __shfl_xor_sync(0xffffffffu, rsd, off);
    float rsf = (float)rsd;
    __syncwarp();

    // pass 2: numerator; lane owns 4 output cols; fp16 m gathers (8B/lane/edge)
    float4 acc = make_float4(0.f, 0.f, 0.f, 0.f);
    const uint2* __restrict__ MH = (const uint2*)g_mh;
#pragma unroll 2
    for (int t = 0; t < d; t++) {
        int2 p = g_pairs[start + t];
        float e;
        if (t < MAXD) {
            e = ebuf[w][t];
        } else {
            float z = si + g_sdst[p.x];
            e = z >= 0.f ? z : 0.2f * z;
        }
        float att = e / rsf;
        float tt = __int_as_float(p.y) * att;
        uint2 hv = __ldg(&MH[(size_t)p.x * 32 + lane]);
        __half2 h0 = *(__half2*)&hv.x;
        __half2 h1 = *(__half2*)&hv.y;
        float2 f0 = __half22float2(h0);
        float2 f1 = __half22float2(h1);
        acc.x = fmaf(tt, f0.x, acc.x);
        acc.y = fmaf(tt, f0.y, acc.y);
        acc.z = fmaf(tt, f1.x, acc.z);
        acc.w = fmaf(tt, f1.y, acc.w);
    }
    *((float4*)(out + (size_t)i * D_OUT) + lane) = acc;
}

// ================= launch (fork/join; GEMM is 4th launch for ncu capture) =================
struct HbsRes {
    cudaStream_t s2;
    cudaEvent_t evFork, evJoin;
    HbsRes() {
        cudaStreamCreateWithFlags(&s2, cudaStreamNonBlocking);
        cudaEventCreateWithFlags(&evFork, cudaEventDisableTiming);
        cudaEventCreateWithFlags(&evJoin, cudaEventDisableTiming);
    }
};

extern "C" void kernel_launch(void* const* d_in, const int* in_sizes, int n_in,
                              void* d_out, int out_size) {
    static HbsRes res;

    const float* x      = (const float*)d_in[0];
    const float* W      = (const float*)d_in[1];
    const float* a      = (const float*)d_in[2];
    const float* n_vals = (const float*)d_in[3];
    const int*   n_src  = (const int*)d_in[4];
    const int*   n_dst  = (const int*)d_in[5];
    float* out = (float*)d_out;

    cudaEventRecord(res.evFork, 0);
    cudaStreamWaitEvent(res.s2, res.evFork, 0);

    // launches 1-3: CSR build on s2 (overlaps GEMM)
    hist_kernel<<<(N_EDGES / 8 + 255) / 256, 256, 0, res.s2>>>(n_src);
    alloc_kernel<<<(N_CELLS + 255) / 256, 256, 0, res.s2>>>();
    scatter_kernel<<<(N_EDGES / 4 + 255) / 256, 256, 0, res.s2>>>(n_src, n_dst, n_vals);
    cudaEventRecord(res.evJoin, res.s2);

    // launch 4: GEMM (ncu capture target)
    const int gemm_blocks = (N_CELLS + BM - 1) / BM;            // 391
    gemm_kernel<<<gemm_blocks, 256>>>(x, W);

    // launch 5: scores
    const int warp_blocks = (N_CELLS * 32 + 255) / 256;         // 6250
    score_kernel<<<warp_blocks, 256>>>(a);

    // launch 6: aggregate after join
    cudaStreamWaitEvent(0, res.evJoin, 0);
    agg_kernel<<<warp_blocks, 256>>>(out);
}

// round 14
// speedup vs baseline: 1.0168x; 1.0168x over previous
#include <cuda_runtime.h>
#include <cuda_fp16.h>

#define N_CELLS 50000
#define N_EDGES 1600000
#define D_IN 256
#define D_OUT 128
#define MAXD 128

// ---- scratch (device globals; no allocation allowed) ----
__device__ float  g_m[N_CELLS * D_OUT];     // x @ W fp32 (frozen numerics; feeds scores)
__device__ __half g_mh[N_CELLS * D_OUT];    // fp16 copy (feeds agg numerator)
__device__ float  g_ssrc[N_CELLS];
__device__ float  g_sdst[N_CELLS];
__device__ int    g_cnt[N_CELLS];           // zeroed by agg at end of each run
__device__ int    g_rowstart[N_CELLS];
__device__ int    g_fill[N_CELLS];
__device__ int    g_total;
__device__ int2   g_pairs[N_EDGES];         // (dst, float_bits(n_val)) grouped by src

// ---- packed f32x2 helpers (FFMA2: each half IEEE fp32 RN, bit == scalar fmaf) ----
__device__ __forceinline__ unsigned long long pk2(float lo, float hi) {
    unsigned long long r;
    asm("mov.b64 %0, {%1, %2};" : "=l"(r) : "f"(lo), "f"(hi));
    return r;
}
__device__ __forceinline__ void upk2(unsigned long long v, float& lo, float& hi) {
    asm("mov.b64 {%0, %1}, %2;" : "=f"(lo), "=f"(hi) : "l"(v));
}
__device__ __forceinline__ unsigned long long ffma2(unsigned long long a,
                                                    unsigned long long b,
                                                    unsigned long long c) {
    unsigned long long d;
    asm("fma.rn.f32x2 %0, %1, %2, %3;" : "=l"(d) : "l"(a), "l"(b), "l"(c));
    return d;
}

// ================= GEMM: g_m = x @ W (R10 version: pipelined, FFMA2, frozen k-order) =================
#define BM 128
#define BN 128
#define BK 16

__global__ __launch_bounds__(256) void gemm_kernel(const float* __restrict__ x,
                                                   const float* __restrict__ W) {
    __shared__ float As[BK][BM + 4];
    __shared__ float Bs[BK][BN];
    const int tid = threadIdx.x;
    const int blockRow = blockIdx.x * BM;
    const int tx = tid & 15;
    const int ty = tid >> 4;

    unsigned long long acc2[8][4];
#pragma unroll
    for (int r = 0; r < 8; r++)
#pragma unroll
        for (int c = 0; c < 4; c++) acc2[r][c] = 0ull;

    const int rowA = tid >> 2;          // 0..63
    const int colA = (tid & 3) << 2;    // 0,4,8,12
    const int rowB = tid >> 5;          // 0..7
    const int colB = (tid & 31) << 2;   // 0..124

    const int grA0 = blockRow + rowA;
    const int grA1 = blockRow + rowA + 64;
    const bool okA0 = grA0 < N_CELLS;
    const bool okA1 = grA1 < N_CELLS;
    const float* pA0 = x + (size_t)(okA0 ? grA0 : 0) * D_IN + colA;
    const float* pA1 = x + (size_t)(okA1 ? grA1 : 0) * D_IN + colA;
    const float* pB0 = W + (size_t)rowB * D_OUT + colB;
    const float* pB1 = W + (size_t)(rowB + 8) * D_OUT + colB;

    {
        float4 a0 = okA0 ? *(const float4*)pA0 : make_float4(0.f, 0.f, 0.f, 0.f);
        float4 a1 = okA1 ? *(const float4*)pA1 : make_float4(0.f, 0.f, 0.f, 0.f);
        float4 b0 = *(const float4*)pB0;
        float4 b1 = *(const float4*)pB1;
        As[colA + 0][rowA] = a0.x; As[colA + 1][rowA] = a0.y;
        As[colA + 2][rowA] = a0.z; As[colA + 3][rowA] = a0.w;
        As[colA + 0][rowA + 64] = a1.x; As[colA + 1][rowA + 64] = a1.y;
        As[colA + 2][rowA + 64] = a1.z; As[colA + 3][rowA + 64] = a1.w;
        *(float4*)(&Bs[rowB][colB]) = b0;
        *(float4*)(&Bs[rowB + 8][colB]) = b1;
    }
    __syncthreads();

    for (int kk = 0; kk < D_IN; kk += BK) {
        float4 na0, na1, nb0, nb1;
        const bool more = (kk + BK) < D_IN;
        if (more) {
            na0 = okA0 ? *(const float4*)(pA0 + kk + BK) : make_float4(0.f, 0.f, 0.f, 0.f);
            na1 = okA1 ? *(const float4*)(pA1 + kk + BK) : make_float4(0.f, 0.f, 0.f, 0.f);
            nb0 = *(const float4*)(pB0 + (size_t)(kk + BK) * D_OUT);
            nb1 = *(const float4*)(pB1 + (size_t)(kk + BK) * D_OUT);
        }
#pragma unroll
        for (int k = 0; k < BK; k++) {
            float4 a0 = *(const float4*)(&As[k][ty * 8]);
            float4 a1 = *(const float4*)(&As[k][ty * 8 + 4]);
            float4 b0 = *(const float4*)(&Bs[k][tx * 8]);
            float4 b1 = *(const float4*)(&Bs[k][tx * 8 + 4]);
            unsigned long long nn[4] = {pk2(b0.x, b0.y), pk2(b0.z, b0.w),
                                        pk2(b1.x, b1.y), pk2(b1.z, b1.w)};
            float mA[8] = {a0.x, a0.y, a0.z, a0.w, a1.x, a1.y, a1.z, a1.w};
#pragma unroll
            for (int r = 0; r < 8; r++) {
                unsigned long long md = pk2(mA[r], mA[r]);
#pragma unroll
                for (int c = 0; c < 4; c++)
                    acc2[r][c] = ffma2(md, nn[c], acc2[r][c]);
            }
        }
        __syncthreads();
        if (more) {
            As[colA + 0][rowA] = na0.x; As[colA + 1][rowA] = na0.y;
            As[colA + 2][rowA] = na0.z; As[colA + 3][rowA] = na0.w;
            As[colA + 0][rowA + 64] = na1.x; As[colA + 1][rowA + 64] = na1.y;
            As[colA + 2][rowA + 64] = na1.z; As[colA + 3][rowA + 64] = na1.w;
            *(float4*)(&Bs[rowB][colB]) = nb0;
            *(float4*)(&Bs[rowB + 8][colB]) = nb1;
            __syncthreads();
        }
    }

#pragma unroll
    for (int r = 0; r < 8; r++) {
        int gr = blockRow + ty * 8 + r;
        if (gr < N_CELLS) {
            float f[8];
            upk2(acc2[r][0], f[0], f[1]);
            upk2(acc2[r][1], f[2], f[3]);
            upk2(acc2[r][2], f[4], f[5]);
            upk2(acc2[r][3], f[6], f[7]);
            float* dst = g_m + (size_t)gr * D_OUT + tx * 8;
            *(float4*)dst = make_float4(f[0], f[1], f[2], f[3]);
            *(float4*)(dst + 4) = make_float4(f[4], f[5], f[6], f[7]);
            __half2 h0 = __floats2half2_rn(f[0], f[1]);
            __half2 h1 = __floats2half2_rn(f[2], f[3]);
            __half2 h2 = __floats2half2_rn(f[4], f[5]);
            __half2 h3 = __floats2half2_rn(f[6], f[7]);
            uint4 hv;
            hv.x = *(unsigned int*)&h0;
            hv.y = *(unsigned int*)&h1;
            hv.z = *(unsigned int*)&h2;
            hv.w = *(unsigned int*)&h3;
            *(uint4*)(g_mh + (size_t)gr * D_OUT + tx * 8) = hv;
        }
    }
}

// ================= scores: cublas-gemv emulation (FROZEN numerics) =================
__global__ __launch_bounds__(256) void score_kernel(const float* __restrict__ a) {
    __shared__ float sa[2 * D_OUT];
    for (int j = threadIdx.x; j < 2 * D_OUT; j += blockDim.x) sa[j] = a[j];
    __syncthreads();
    int row = (blockIdx.x * blockDim.x + threadIdx.x) >> 5;
    int l = threadIdx.x & 31;
    if (row >= N_CELLS) return;
    const float* __restrict__ mr = g_m + (size_t)row * D_OUT;

    float m0 = __ldg(mr + l);
    float m1 = __ldg(mr + l + 32);
    float m2 = __ldg(mr + l + 64);
    float m3 = __ldg(mr + l + 96);

    float ss = fmaf(m0, sa[l], 0.f);
    ss = fmaf(m1, sa[l + 32], ss);
    ss = fmaf(m2, sa[l + 64], ss);
    ss = fmaf(m3, sa[l + 96], ss);

    float sd = fmaf(m0, sa[D_OUT + l], 0.f);
    sd = fmaf(m1, sa[D_OUT + l + 32], sd);
    sd = fmaf(m2, sa[D_OUT + l + 64], sd);
    sd = fmaf(m3, sa[D_OUT + l + 96], sd);

#pragma unroll
    for (int off = 16; off > 0; off >>= 1) {
        ss += __shfl_down_sync(0xffffffffu, ss, off);
        sd += __shfl_down_sync(0xffffffffu, sd, off);
    }
    if (l == 0) {
        g_ssrc[row] = ss;
        g_sdst[row] = sd;
    }
}

// ================= CSR build (scan-free) =================
__global__ void hist_kernel(const int* __restrict__ n_src) {
    if (blockIdx.x == 0 && threadIdx.x == 0) g_total = 0;
    int e = (blockIdx.x * blockDim.x + threadIdx.x) * 8;
    if (e < N_EDGES) {
        int4 s0 = *(const int4*)(n_src + e);
        int4 s1 = *(const int4*)(n_src + e + 4);
        atomicAdd(&g_cnt[s0.x], 1);
        atomicAdd(&g_cnt[s0.y], 1);
        atomicAdd(&g_cnt[s0.z], 1);
        atomicAdd(&g_cnt[s0.w], 1);
        atomicAdd(&g_cnt[s1.x], 1);
        atomicAdd(&g_cnt[s1.y], 1);
        atomicAdd(&g_cnt[s1.z], 1);
        atomicAdd(&g_cnt[s1.w], 1);
    }
}

__global__ __launch_bounds__(256) void alloc_kernel() {
    int i = blockIdx.x * blockDim.x + threadIdx.x;
    int lane = threadIdx.x & 31;
    int cnt = (i < N_CELLS) ? g_cnt[i] : 0;
    int xv = cnt;
#pragma unroll
    for (int off = 1; off < 32; off <<= 1) {
        int y = __shfl_up_sync(0xffffffffu, xv, off);
        if (lane >= off) xv += y;
    }
    int excl = xv - cnt;
    int wtotal = __shfl_sync(0xffffffffu, xv, 31);
    int base = 0;
    if (lane == 0) base = atomicAdd(&g_total, wtotal);
    base = __shfl_sync(0xffffffffu, base, 0);
    if (i < N_CELLS) {
        int s = base + excl;
        g_rowstart[i] = s;
        g_fill[i] = s;
    }
}

__global__ void scatter_kernel(const int* __restrict__ n_src,
                               const int* __restrict__ n_dst,
                               const float* __restrict__ n_vals) {
    int e = (blockIdx.x * blockDim.x + threadIdx.x) * 4;
    if (e < N_EDGES) {
        int4 s = *(const int4*)(n_src + e);
        int4 d = *(const int4*)(n_dst + e);
        float4 v = *(const float4*)(n_vals + e);
        int p0 = atomicAdd(&g_fill[s.x], 1);
        int p1 = atomicAdd(&g_fill[s.y], 1);
        int p2 = atomicAdd(&g_fill[s.z], 1);
        int p3 = atomicAdd(&g_fill[s.w], 1);
        g_pairs[p0] = make_int2(d.x, __float_as_int(v.x));
        g_pairs[p1] = make_int2(d.y, __float_as_int(v.y));
        g_pairs[p2] = make_int2(d.z, __float_as_int(v.z));
        g_pairs[p3] = make_int2(d.w, __float_as_int(v.w));
    }
}

// ================= aggregation =================
// pass1: per-lane e + fp64 rs; then each lane computes c = nv*(e/rsf) ONCE per
// owned edge (division count /32, parallel) into smem. pass2: broadcast c +
// fp16 m gather + 4 FFMA per lane. Bitwise-identical output to R10 agg.
__global__ __launch_bounds__(256) void agg_kernel(float* __restrict__ out) {
    __shared__ float cbuf[8][MAXD];
    const int w = threadIdx.x >> 5;
    int i = (blockIdx.x * blockDim.x + threadIdx.x) >> 5;
    int lane = threadIdx.x & 31;
    if (i >= N_CELLS) return;
    int start = g_rowstart[i];
    int d = g_cnt[i];
    if (lane == 0) g_cnt[i] = 0;    // reset for next run (replaces zero_kernel)
    float si = g_ssrc[i];

    // pass 1: e per owned edge (kept in regs) + fp64 rs
    float e_reg[4], nv_reg[4];
    int nown = 0;
    double rsd = 0.0;
    for (int t = lane; t < d; t += 32) {
        int2 p = g_pairs[start + t];
        float z = si + g_sdst[p.x];
        float e = z >= 0.f ? z : 0.2f * z;
        if (nown < 4) { e_reg[nown] = e; nv_reg[nown] = __int_as_float(p.y); }
        rsd += (double)e;
        nown++;
    }
#pragma unroll
    for (int off = 16; off > 0; off >>= 1)
        rsd += __shfl_xor_sync(0xffffffffu, rsd, off);
    float rsf = (float)rsd;

    // coefficients: one division per edge, lane-parallel
    {
        int cnt = 0;
        for (int t = lane; t < d && cnt < 4; t += 32, cnt++) {
            float att = e_reg[cnt] / rsf;
            cbuf[w][t] = nv_reg[cnt] * att;
        }
    }
    __syncwarp();

    // pass 2: broadcast coefficient + fp16 m gather
    float4 acc = make_float4(0.f, 0.f, 0.f, 0.f);
    const uint2* __restrict__ MH = (const uint2*)g_mh;
#pragma unroll 2
    for (int t = 0; t < d; t++) {
        int2 p = g_pairs[start + t];
        float tt;
        if (t < MAXD) {
            tt = cbuf[w][t];
        } else {            // degree > 128: recompute (identical ops)
            float z = si + g_sdst[p.x];
            float e = z >= 0.f ? z : 0.2f * z;
            tt = __int_as_float(p.y) * (e / rsf);
        }
        uint2 hv = __ldg(&MH[(size_t)p.x * 32 + lane]);
        __half2 h0 = *(__half2*)&hv.x;
        __half2 h1 = *(__half2*)&hv.y;
        float2 f0 = __half22float2(h0);
        float2 f1 = __half22float2(h1);
        acc.x = fmaf(tt, f0.x, acc.x);
        acc.y = fmaf(tt, f0.y, acc.y);
        acc.z = fmaf(tt, f1.x, acc.z);
        acc.w = fmaf(tt, f1.y, acc.w);
    }
    *((float4*)(out + (size_t)i * D_OUT) + lane) = acc;
}

// ================= launch (fork/join; GEMM is 4th launch for ncu capture) =================
struct HbsRes {
    cudaStream_t s2;
    cudaEvent_t evFork, evJoin;
    HbsRes() {
        cudaStreamCreateWithFlags(&s2, cudaStreamNonBlocking);
        cudaEventCreateWithFlags(&evFork, cudaEventDisableTiming);
        cudaEventCreateWithFlags(&evJoin, cudaEventDisableTiming);
    }
};

extern "C" void kernel_launch(void* const* d_in, const int* in_sizes, int n_in,
                              void* d_out, int out_size) {
    static HbsRes res;

    const float* x      = (const float*)d_in[0];
    const float* W      = (const float*)d_in[1];
    const float* a      = (const float*)d_in[2];
    const float* n_vals = (const float*)d_in[3];
    const int*   n_src  = (const int*)d_in[4];
    const int*   n_dst  = (const int*)d_in[5];
    float* out = (float*)d_out;

    cudaEventRecord(res.evFork, 0);
    cudaStreamWaitEvent(res.s2, res.evFork, 0);

    // launches 1-3: CSR build on s2 (overlaps GEMM)
    hist_kernel<<<(N_EDGES / 8 + 255) / 256, 256, 0, res.s2>>>(n_src);
    alloc_kernel<<<(N_CELLS + 255) / 256, 256, 0, res.s2>>>();
    scatter_kernel<<<(N_EDGES / 4 + 255) / 256, 256, 0, res.s2>>>(n_src, n_dst, n_vals);
    cudaEventRecord(res.evJoin, res.s2);

    // launch 4: GEMM (ncu capture target)
    const int gemm_blocks = (N_CELLS + BM - 1) / BM;            // 391
    gemm_kernel<<<gemm_blocks, 256>>>(x, W);

    // launch 5: scores
    const int warp_blocks = (N_CELLS * 32 + 255) / 256;         // 6250
    score_kernel<<<warp_blocks, 256>>>(a);

    // launch 6: aggregate after join
    cudaStreamWaitEvent(0, res.evJoin, 0);
    agg_kernel<<<warp_blocks, 256>>>(out);
}

// round 15
// speedup vs baseline: 1.4009x; 1.3777x over previous
#include <cuda_runtime.h>
#include <cuda_fp16.h>

#define N_CELLS 50000
#define N_EDGES 1600000
#define D_IN 256
#define D_OUT 128
#define MAXD 128

// ---- scratch (device globals; no allocation allowed) ----
__device__ float  g_m[N_CELLS * D_OUT];     // x @ W fp32 (frozen numerics; feeds scores)
__device__ __half g_mh[N_CELLS * D_OUT];    // fp16 copy (feeds agg numerator)
__device__ float  g_ssrc[N_CELLS];
__device__ float  g_sdst[N_CELLS];
__device__ int    g_cnt[N_CELLS];
__device__ int    g_rowstart[N_CELLS];
__device__ int    g_fill[N_CELLS];
__device__ int    g_total;
__device__ int2   g_pairs[N_EDGES];         // (dst, float_bits(n_val)) grouped by src

// ---- packed f32x2 helpers (FFMA2: each half IEEE fp32 RN, bit == scalar fmaf) ----
__device__ __forceinline__ unsigned long long pk2(float lo, float hi) {
    unsigned long long r;
    asm("mov.b64 %0, {%1, %2};" : "=l"(r) : "f"(lo), "f"(hi));
    return r;
}
__device__ __forceinline__ void upk2(unsigned long long v, float& lo, float& hi) {
    asm("mov.b64 {%0, %1}, %2;" : "=f"(lo), "=f"(hi) : "l"(v));
}
__device__ __forceinline__ unsigned long long ffma2(unsigned long long a,
                                                    unsigned long long b,
                                                    unsigned long long c) {
    unsigned long long d;
    asm("fma.rn.f32x2 %0, %1, %2, %3;" : "=l"(d) : "l"(a), "l"(b), "l"(c));
    return d;
}

// ================= GEMM: g_m = x @ W (software-pipelined, FFMA2, frozen k-order) =================
#define BM 128
#define BN 128
#define BK 16

__global__ __launch_bounds__(256) void gemm_kernel(const float* __restrict__ x,
                                                   const float* __restrict__ W) {
    __shared__ float As[BK][BM + 4];
    __shared__ float Bs[BK][BN];
    const int tid = threadIdx.x;
    const int blockRow = blockIdx.x * BM;
    const int tx = tid & 15;
    const int ty = tid >> 4;

    unsigned long long acc2[8][4];
#pragma unroll
    for (int r = 0; r < 8; r++)
#pragma unroll
        for (int c = 0; c < 4; c++) acc2[r][c] = 0ull;

    const int rowA = tid >> 2;          // 0..63
    const int colA = (tid & 3) << 2;    // 0,4,8,12
    const int rowB = tid >> 5;          // 0..7
    const int colB = (tid & 31) << 2;   // 0..124

    const int grA0 = blockRow + rowA;
    const int grA1 = blockRow + rowA + 64;
    const bool okA0 = grA0 < N_CELLS;
    const bool okA1 = grA1 < N_CELLS;
    const float* pA0 = x + (size_t)(okA0 ? grA0 : 0) * D_IN + colA;
    const float* pA1 = x + (size_t)(okA1 ? grA1 : 0) * D_IN + colA;
    const float* pB0 = W + (size_t)rowB * D_OUT + colB;
    const float* pB1 = W + (size_t)(rowB + 8) * D_OUT + colB;

    // prologue: tile kk=0 into smem
    {
        float4 a0 = okA0 ? *(const float4*)pA0 : make_float4(0.f, 0.f, 0.f, 0.f);
        float4 a1 = okA1 ? *(const float4*)pA1 : make_float4(0.f, 0.f, 0.f, 0.f);
        float4 b0 = *(const float4*)pB0;
        float4 b1 = *(const float4*)pB1;
        As[colA + 0][rowA] = a0.x; As[colA + 1][rowA] = a0.y;
        As[colA + 2][rowA] = a0.z; As[colA + 3][rowA] = a0.w;
        As[colA + 0][rowA + 64] = a1.x; As[colA + 1][rowA + 64] = a1.y;
        As[colA + 2][rowA + 64] = a1.z; As[colA + 3][rowA + 64] = a1.w;
        *(float4*)(&Bs[rowB][colB]) = b0;
        *(float4*)(&Bs[rowB + 8][colB]) = b1;
    }
    __syncthreads();

    for (int kk = 0; kk < D_IN; kk += BK) {
        // prefetch next tile into registers
        float4 na0, na1, nb0, nb1;
        const bool more = (kk + BK) < D_IN;
        if (more) {
            na0 = okA0 ? *(const float4*)(pA0 + kk + BK) : make_float4(0.f, 0.f, 0.f, 0.f);
            na1 = okA1 ? *(const float4*)(pA1 + kk + BK) : make_float4(0.f, 0.f, 0.f, 0.f);
            nb0 = *(const float4*)(pB0 + (size_t)(kk + BK) * D_OUT);
            nb1 = *(const float4*)(pB1 + (size_t)(kk + BK) * D_OUT);
        }
#pragma unroll
        for (int k = 0; k < BK; k++) {
            float4 a0 = *(const float4*)(&As[k][ty * 8]);
            float4 a1 = *(const float4*)(&As[k][ty * 8 + 4]);
            float4 b0 = *(const float4*)(&Bs[k][tx * 8]);
            float4 b1 = *(const float4*)(&Bs[k][tx * 8 + 4]);
            unsigned long long nn[4] = {pk2(b0.x, b0.y), pk2(b0.z, b0.w),
                                        pk2(b1.x, b1.y), pk2(b1.z, b1.w)};
            float mA[8] = {a0.x, a0.y, a0.z, a0.w, a1.x, a1.y, a1.z, a1.w};
#pragma unroll
            for (int r = 0; r < 8; r++) {
                unsigned long long md = pk2(mA[r], mA[r]);
#pragma unroll
                for (int c = 0; c < 4; c++)
                    acc2[r][c] = ffma2(md, nn[c], acc2[r][c]);
            }
        }
        __syncthreads();
        if (more) {
            As[colA + 0][rowA] = na0.x; As[colA + 1][rowA] = na0.y;
            As[colA + 2][rowA] = na0.z; As[colA + 3][rowA] = na0.w;
            As[colA + 0][rowA + 64] = na1.x; As[colA + 1][rowA + 64] = na1.y;
            As[colA + 2][rowA + 64] = na1.z; As[colA + 3][rowA + 64] = na1.w;
            *(float4*)(&Bs[rowB][colB]) = nb0;
            *(float4*)(&Bs[rowB + 8][colB]) = nb1;
            __syncthreads();
        }
    }

#pragma unroll
    for (int r = 0; r < 8; r++) {
        int gr = blockRow + ty * 8 + r;
        if (gr < N_CELLS) {
            float f[8];
            upk2(acc2[r][0], f[0], f[1]);
            upk2(acc2[r][1], f[2], f[3]);
            upk2(acc2[r][2], f[4], f[5]);
            upk2(acc2[r][3], f[6], f[7]);
            float* dst = g_m + (size_t)gr * D_OUT + tx * 8;
            *(float4*)dst = make_float4(f[0], f[1], f[2], f[3]);
            *(float4*)(dst + 4) = make_float4(f[4], f[5], f[6], f[7]);
            __half2 h0 = __floats2half2_rn(f[0], f[1]);
            __half2 h1 = __floats2half2_rn(f[2], f[3]);
            __half2 h2 = __floats2half2_rn(f[4], f[5]);
            __half2 h3 = __floats2half2_rn(f[6], f[7]);
            uint4 hv;
            hv.x = *(unsigned int*)&h0;
            hv.y = *(unsigned int*)&h1;
            hv.z = *(unsigned int*)&h2;
            hv.w = *(unsigned int*)&h3;
            *(uint4*)(g_mh + (size_t)gr * D_OUT + tx * 8) = hv;
        }
    }
}

// ================= scores: cublas-gemv emulation (FROZEN numerics) =================
__global__ __launch_bounds__(256) void score_kernel(const float* __restrict__ a) {
    __shared__ float sa[2 * D_OUT];
    for (int j = threadIdx.x; j < 2 * D_OUT; j += blockDim.x) sa[j] = a[j];
    __syncthreads();
    int row = (blockIdx.x * blockDim.x + threadIdx.x) >> 5;
    int l = threadIdx.x & 31;
    if (row >= N_CELLS) return;
    const float* __restrict__ mr = g_m + (size_t)row * D_OUT;

    float m0 = __ldg(mr + l);
    float m1 = __ldg(mr + l + 32);
    float m2 = __ldg(mr + l + 64);
    float m3 = __ldg(mr + l + 96);

    float ss = fmaf(m0, sa[l], 0.f);
    ss = fmaf(m1, sa[l + 32], ss);
    ss = fmaf(m2, sa[l + 64], ss);
    ss = fmaf(m3, sa[l + 96], ss);

    float sd = fmaf(m0, sa[D_OUT + l], 0.f);
    sd = fmaf(m1, sa[D_OUT + l + 32], sd);
    sd = fmaf(m2, sa[D_OUT + l + 64], sd);
    sd = fmaf(m3, sa[D_OUT + l + 96], sd);

#pragma unroll
    for (int off = 16; off > 0; off >>= 1) {
        ss += __shfl_down_sync(0xffffffffu, ss, off);
        sd += __shfl_down_sync(0xffffffffu, sd, off);
    }
    if (l == 0) {
        g_ssrc[row] = ss;
        g_sdst[row] = sd;
    }
}

// ================= CSR build (scan-free, 4 edges/thread) =================
__global__ void zero_kernel() {
    int i = blockIdx.x * blockDim.x + threadIdx.x;
    if (i < N_CELLS) g_cnt[i] = 0;
    if (i == 0) g_total = 0;
}

__global__ void hist_kernel(const int* __restrict__ n_src) {
    int e = (blockIdx.x * blockDim.x + threadIdx.x) * 4;
    if (e < N_EDGES) {
        int4 s = *(const int4*)(n_src + e);
        atomicAdd(&g_cnt[s.x], 1);
        atomicAdd(&g_cnt[s.y], 1);
        atomicAdd(&g_cnt[s.z], 1);
        atomicAdd(&g_cnt[s.w], 1);
    }
}

__global__ __launch_bounds__(256) void alloc_kernel() {
    int i = blockIdx.x * blockDim.x + threadIdx.x;
    int lane = threadIdx.x & 31;
    int cnt = (i < N_CELLS) ? g_cnt[i] : 0;
    int xv = cnt;
#pragma unroll
    for (int off = 1; off < 32; off <<= 1) {
        int y = __shfl_up_sync(0xffffffffu, xv, off);
        if (lane >= off) xv += y;
    }
    int excl = xv - cnt;
    int wtotal = __shfl_sync(0xffffffffu, xv, 31);
    int base = 0;
    if (lane == 0) base = atomicAdd(&g_total, wtotal);
    base = __shfl_sync(0xffffffffu, base, 0);
    if (i < N_CELLS) {
        int s = base + excl;
        g_rowstart[i] = s;
        g_fill[i] = s;
    }
}

__global__ void scatter_kernel(const int* __restrict__ n_src,
                               const int* __restrict__ n_dst,
                               const float* __restrict__ n_vals) {
    int e = (blockIdx.x * blockDim.x + threadIdx.x) * 4;
    if (e < N_EDGES) {
        int4 s = *(const int4*)(n_src + e);
        int4 d = *(const int4*)(n_dst + e);
        float4 v = *(const float4*)(n_vals + e);
        int p0 = atomicAdd(&g_fill[s.x], 1);
        int p1 = atomicAdd(&g_fill[s.y], 1);
        int p2 = atomicAdd(&g_fill[s.z], 1);
        int p3 = atomicAdd(&g_fill[s.w], 1);
        g_pairs[p0] = make_int2(d.x, __float_as_int(v.x));
        g_pairs[p1] = make_int2(d.y, __float_as_int(v.y));
        g_pairs[p2] = make_int2(d.z, __float_as_int(v.z));
        g_pairs[p3] = make_int2(d.w, __float_as_int(v.w));
    }
}

// ================= aggregation: one warp per cell (denominator FROZEN; numerator fp16 m) =================
__global__ __launch_bounds__(256) void agg_kernel(float* __restrict__ out) {
    __shared__ float ebuf[8][MAXD];
    const int w = threadIdx.x >> 5;
    int i = (blockIdx.x * blockDim.x + threadIdx.x) >> 5;
    int lane = threadIdx.x & 31;
    if (i >= N_CELLS) return;
    int start = g_rowstart[i];
    int d = g_cnt[i];
    int end = start + d;
    float si = g_ssrc[i];

    // pass 1: e values (cached in smem) + fp64 rs
    double rsd = 0.0;
    for (int j = start + lane; j < end; j += 32) {
        int dst = g_pairs[j].x;
        float z = si + g_sdst[dst];
        float e = z >= 0.f ? z : 0.2f * z;
        int t = j - start;
        if (t < MAXD) ebuf[w][t] = e;
        rsd += (double)e;
    }
#pragma unroll
    for (int off = 16; off > 0; off >>= 1)
        rsd += __shfl_xor_sync(0xffffffffu, rsd, off);
    float rsf = (float)rsd;
    __syncwarp();

    // pass 2: numerator; lane owns 4 output cols; fp16 m gathers (8B/lane/edge)
    float4 acc = make_float4(0.f, 0.f, 0.f, 0.f);
    const uint2* __restrict__ MH = (const uint2*)g_mh;
#pragma unroll 2
    for (int t = 0; t < d; t++) {
        int2 p = g_pairs[start + t];
        float e;
        if (t < MAXD) {
            e = ebuf[w][t];
        } else {
            float z = si + g_sdst[p.x];
            e = z >= 0.f ? z : 0.2f * z;
        }
        float att = e / rsf;
        float tt = __int_as_float(p.y) * att;
        uint2 hv = __ldg(&MH[(size_t)p.x * 32 + lane]);
        __half2 h0 = *(__half2*)&hv.x;
        __half2 h1 = *(__half2*)&hv.y;
        float2 f0 = __half22float2(h0);
        float2 f1 = __half22float2(h1);
        acc.x = fmaf(tt, f0.x, acc.x);
        acc.y = fmaf(tt, f0.y, acc.y);
        acc.z = fmaf(tt, f1.x, acc.z);
        acc.w = fmaf(tt, f1.y, acc.w);
    }
    *((float4*)(out + (size_t)i * D_OUT) + lane) = acc;
}

// ================= launch (fork/join: CSR build overlaps GEMM) =================
struct HbsRes {
    cudaStream_t s2;
    cudaEvent_t evFork, evJoin;
    HbsRes() {
        cudaStreamCreateWithFlags(&s2, cudaStreamNonBlocking);
        cudaEventCreateWithFlags(&evFork, cudaEventDisableTiming);
        cudaEventCreateWithFlags(&evJoin, cudaEventDisableTiming);
    }
};

extern "C" void kernel_launch(void* const* d_in, const int* in_sizes, int n_in,
                              void* d_out, int out_size) {
    static HbsRes res;

    const float* x      = (const float*)d_in[0];
    const float* W      = (const float*)d_in[1];
    const float* a      = (const float*)d_in[2];
    const float* n_vals = (const float*)d_in[3];
    const int*   n_src  = (const int*)d_in[4];
    const int*   n_dst  = (const int*)d_in[5];
    float* out = (float*)d_out;

    cudaEventRecord(res.evFork, 0);
    cudaStreamWaitEvent(res.s2, res.evFork, 0);

    zero_kernel<<<(N_CELLS + 255) / 256, 256, 0, res.s2>>>();
    hist_kernel<<<(N_EDGES / 4 + 255) / 256, 256, 0, res.s2>>>(n_src);
    alloc_kernel<<<(N_CELLS + 255) / 256, 256, 0, res.s2>>>();
    scatter_kernel<<<(N_EDGES / 4 + 255) / 256, 256, 0, res.s2>>>(n_src, n_dst, n_vals);
    cudaEventRecord(res.evJoin, res.s2);

    const int gemm_blocks = (N_CELLS + BM - 1) / BM;            // 391
    gemm_kernel<<<gemm_blocks, 256>>>(x, W);

    const int warp_blocks = (N_CELLS * 32 + 255) / 256;         // 6250
    score_kernel<<<warp_blocks, 256>>>(a);

    cudaStreamWaitEvent(0, res.evJoin, 0);
    agg_kernel<<<warp_blocks, 256>>>(out);
}

// round 16
// speedup vs baseline: 1.5003x; 1.0709x over previous
#include <cuda_runtime.h>
#include <cuda_fp16.h>

#define N_CELLS 50000
#define N_EDGES 1600000
#define D_IN 256
#define D_OUT 128
#define MAXD 128

// ---- scratch (device globals; no allocation allowed) ----
__device__ float  g_m[N_CELLS * D_OUT];     // x @ W fp32 (frozen numerics; feeds scores)
__device__ __half g_mh[N_CELLS * D_OUT];    // fp16 copy (feeds agg numerator)
__device__ float  g_ssrc[N_CELLS];
__device__ float  g_sdst[N_CELLS];
__device__ int    g_cnt[N_CELLS];
__device__ int    g_rowstart[N_CELLS];
__device__ int    g_fill[N_CELLS];
__device__ int    g_total;
__device__ int2   g_pairs[N_EDGES];         // (dst, float_bits(n_val)) grouped by src

// ---- packed f32x2 helpers (FFMA2: each half IEEE fp32 RN, bit == scalar fmaf) ----
__device__ __forceinline__ unsigned long long pk2(float lo, float hi) {
    unsigned long long r;
    asm("mov.b64 %0, {%1, %2};" : "=l"(r) : "f"(lo), "f"(hi));
    return r;
}
__device__ __forceinline__ void upk2(unsigned long long v, float& lo, float& hi) {
    asm("mov.b64 {%0, %1}, %2;" : "=f"(lo), "=f"(hi) : "l"(v));
}
__device__ __forceinline__ unsigned long long ffma2(unsigned long long a,
                                                    unsigned long long b,
                                                    unsigned long long c) {
    unsigned long long d;
    asm("fma.rn.f32x2 %0, %1, %2, %3;" : "=l"(d) : "l"(a), "l"(b), "l"(c));
    return d;
}

// ================= GEMM: g_m = x @ W (software-pipelined, FFMA2, frozen k-order) =================
#define BM 128
#define BN 128
#define BK 16

__global__ __launch_bounds__(256) void gemm_kernel(const float* __restrict__ x,
                                                   const float* __restrict__ W) {
    __shared__ float As[BK][BM + 4];
    __shared__ float Bs[BK][BN];
    const int tid = threadIdx.x;
    const int blockRow = blockIdx.x * BM;
    const int tx = tid & 15;
    const int ty = tid >> 4;

    unsigned long long acc2[8][4];
#pragma unroll
    for (int r = 0; r < 8; r++)
#pragma unroll
        for (int c = 0; c < 4; c++) acc2[r][c] = 0ull;

    const int rowA = tid >> 2;          // 0..63
    const int colA = (tid & 3) << 2;    // 0,4,8,12
    const int rowB = tid >> 5;          // 0..7
    const int colB = (tid & 31) << 2;   // 0..124

    const int grA0 = blockRow + rowA;
    const int grA1 = blockRow + rowA + 64;
    const bool okA0 = grA0 < N_CELLS;
    const bool okA1 = grA1 < N_CELLS;
    const float* pA0 = x + (size_t)(okA0 ? grA0 : 0) * D_IN + colA;
    const float* pA1 = x + (size_t)(okA1 ? grA1 : 0) * D_IN + colA;
    const float* pB0 = W + (size_t)rowB * D_OUT + colB;
    const float* pB1 = W + (size_t)(rowB + 8) * D_OUT + colB;

    // prologue: tile kk=0 into smem
    {
        float4 a0 = okA0 ? *(const float4*)pA0 : make_float4(0.f, 0.f, 0.f, 0.f);
        float4 a1 = okA1 ? *(const float4*)pA1 : make_float4(0.f, 0.f, 0.f, 0.f);
        float4 b0 = *(const float4*)pB0;
        float4 b1 = *(const float4*)pB1;
        As[colA + 0][rowA] = a0.x; As[colA + 1][rowA] = a0.y;
        As[colA + 2][rowA] = a0.z; As[colA + 3][rowA] = a0.w;
        As[colA + 0][rowA + 64] = a1.x; As[colA + 1][rowA + 64] = a1.y;
        As[colA + 2][rowA + 64] = a1.z; As[colA + 3][rowA + 64] = a1.w;
        *(float4*)(&Bs[rowB][colB]) = b0;
        *(float4*)(&Bs[rowB + 8][colB]) = b1;
    }
    __syncthreads();

    for (int kk = 0; kk < D_IN; kk += BK) {
        // prefetch next tile into registers
        float4 na0, na1, nb0, nb1;
        const bool more = (kk + BK) < D_IN;
        if (more) {
            na0 = okA0 ? *(const float4*)(pA0 + kk + BK) : make_float4(0.f, 0.f, 0.f, 0.f);
            na1 = okA1 ? *(const float4*)(pA1 + kk + BK) : make_float4(0.f, 0.f, 0.f, 0.f);
            nb0 = *(const float4*)(pB0 + (size_t)(kk + BK) * D_OUT);
            nb1 = *(const float4*)(pB1 + (size_t)(kk + BK) * D_OUT);
        }
#pragma unroll
        for (int k = 0; k < BK; k++) {
            float4 a0 = *(const float4*)(&As[k][ty * 8]);
            float4 a1 = *(const float4*)(&As[k][ty * 8 + 4]);
            float4 b0 = *(const float4*)(&Bs[k][tx * 8]);
            float4 b1 = *(const float4*)(&Bs[k][tx * 8 + 4]);
            unsigned long long nn[4] = {pk2(b0.x, b0.y), pk2(b0.z, b0.w),
                                        pk2(b1.x, b1.y), pk2(b1.z, b1.w)};
            float mA[8] = {a0.x, a0.y, a0.z, a0.w, a1.x, a1.y, a1.z, a1.w};
#pragma unroll
            for (int r = 0; r < 8; r++) {
                unsigned long long md = pk2(mA[r], mA[r]);
#pragma unroll
                for (int c = 0; c < 4; c++)
                    acc2[r][c] = ffma2(md, nn[c], acc2[r][c]);
            }
        }
        __syncthreads();
        if (more) {
            As[colA + 0][rowA] = na0.x; As[colA + 1][rowA] = na0.y;
            As[colA + 2][rowA] = na0.z; As[colA + 3][rowA] = na0.w;
            As[colA + 0][rowA + 64] = na1.x; As[colA + 1][rowA + 64] = na1.y;
            As[colA + 2][rowA + 64] = na1.z; As[colA + 3][rowA + 64] = na1.w;
            *(float4*)(&Bs[rowB][colB]) = nb0;
            *(float4*)(&Bs[rowB + 8][colB]) = nb1;
            __syncthreads();
        }
    }

#pragma unroll
    for (int r = 0; r < 8; r++) {
        int gr = blockRow + ty * 8 + r;
        if (gr < N_CELLS) {
            float f[8];
            upk2(acc2[r][0], f[0], f[1]);
            upk2(acc2[r][1], f[2], f[3]);
            upk2(acc2[r][2], f[4], f[5]);
            upk2(acc2[r][3], f[6], f[7]);
            float* dst = g_m + (size_t)gr * D_OUT + tx * 8;
            *(float4*)dst = make_float4(f[0], f[1], f[2], f[3]);
            *(float4*)(dst + 4) = make_float4(f[4], f[5], f[6], f[7]);
            __half2 h0 = __floats2half2_rn(f[0], f[1]);
            __half2 h1 = __floats2half2_rn(f[2], f[3]);
            __half2 h2 = __floats2half2_rn(f[4], f[5]);
            __half2 h3 = __floats2half2_rn(f[6], f[7]);
            uint4 hv;
            hv.x = *(unsigned int*)&h0;
            hv.y = *(unsigned int*)&h1;
            hv.z = *(unsigned int*)&h2;
            hv.w = *(unsigned int*)&h3;
            *(uint4*)(g_mh + (size_t)gr * D_OUT + tx * 8) = hv;
        }
    }
}

// ================= scores: cublas-gemv emulation (FROZEN numerics) =================
__global__ __launch_bounds__(256) void score_kernel(const float* __restrict__ a) {
    __shared__ float sa[2 * D_OUT];
    for (int j = threadIdx.x; j < 2 * D_OUT; j += blockDim.x) sa[j] = a[j];
    __syncthreads();
    int row = (blockIdx.x * blockDim.x + threadIdx.x) >> 5;
    int l = threadIdx.x & 31;
    if (row >= N_CELLS) return;
    const float* __restrict__ mr = g_m + (size_t)row * D_OUT;

    float m0 = __ldg(mr + l);
    float m1 = __ldg(mr + l + 32);
    float m2 = __ldg(mr + l + 64);
    float m3 = __ldg(mr + l + 96);

    float ss = fmaf(m0, sa[l], 0.f);
    ss = fmaf(m1, sa[l + 32], ss);
    ss = fmaf(m2, sa[l + 64], ss);
    ss = fmaf(m3, sa[l + 96], ss);

    float sd = fmaf(m0, sa[D_OUT + l], 0.f);
    sd = fmaf(m1, sa[D_OUT + l + 32], sd);
    sd = fmaf(m2, sa[D_OUT + l + 64], sd);
    sd = fmaf(m3, sa[D_OUT + l + 96], sd);

#pragma unroll
    for (int off = 16; off > 0; off >>= 1) {
        ss += __shfl_down_sync(0xffffffffu, ss, off);
        sd += __shfl_down_sync(0xffffffffu, sd, off);
    }
    if (l == 0) {
        g_ssrc[row] = ss;
        g_sdst[row] = sd;
    }
}

// ================= CSR build (scan-free, 4 edges/thread) =================
__global__ void zero_kernel() {
    int i = blockIdx.x * blockDim.x + threadIdx.x;
    if (i < N_CELLS) g_cnt[i] = 0;
    if (i == 0) g_total = 0;
}

__global__ void hist_kernel(const int* __restrict__ n_src) {
    int e = (blockIdx.x * blockDim.x + threadIdx.x) * 4;
    if (e < N_EDGES) {
        int4 s = *(const int4*)(n_src + e);
        atomicAdd(&g_cnt[s.x], 1);
        atomicAdd(&g_cnt[s.y], 1);
        atomicAdd(&g_cnt[s.z], 1);
        atomicAdd(&g_cnt[s.w], 1);
    }
}

__global__ __launch_bounds__(256) void alloc_kernel() {
    int i = blockIdx.x * blockDim.x + threadIdx.x;
    int lane = threadIdx.x & 31;
    int cnt = (i < N_CELLS) ? g_cnt[i] : 0;
    int xv = cnt;
#pragma unroll
    for (int off = 1; off < 32; off <<= 1) {
        int y = __shfl_up_sync(0xffffffffu, xv, off);
        if (lane >= off) xv += y;
    }
    int excl = xv - cnt;
    int wtotal = __shfl_sync(0xffffffffu, xv, 31);
    int base = 0;
    if (lane == 0) base = atomicAdd(&g_total, wtotal);
    base = __shfl_sync(0xffffffffu, base, 0);
    if (i < N_CELLS) {
        int s = base + excl;
        g_rowstart[i] = s;
        g_fill[i] = s;
    }
}

__global__ void scatter_kernel(const int* __restrict__ n_src,
                               const int* __restrict__ n_dst,
                               const float* __restrict__ n_vals) {
    int e = (blockIdx.x * blockDim.x + threadIdx.x) * 4;
    if (e < N_EDGES) {
        int4 s = *(const int4*)(n_src + e);
        int4 d = *(const int4*)(n_dst + e);
        float4 v = *(const float4*)(n_vals + e);
        int p0 = atomicAdd(&g_fill[s.x], 1);
        int p1 = atomicAdd(&g_fill[s.y], 1);
        int p2 = atomicAdd(&g_fill[s.z], 1);
        int p3 = atomicAdd(&g_fill[s.w], 1);
        g_pairs[p0] = make_int2(d.x, __float_as_int(v.x));
        g_pairs[p1] = make_int2(d.y, __float_as_int(v.y));
        g_pairs[p2] = make_int2(d.z, __float_as_int(v.z));
        g_pairs[p3] = make_int2(d.w, __float_as_int(v.w));
    }
}

// ================= aggregation: one warp per cell =================
// pass1: e -> ebuf, nv -> nbuf (smem, no reg spills), fp64 rs.
// pass1b: lane-parallel in-place coefficient: ebuf[t] = nbuf[t]*(ebuf[t]/rsf)
//         (identical op order to nv*(e/rsf) previously in pass2 -> bit-identical).
// pass2: LDS-broadcast coefficient + fp16 m gather + 4 FFMA per lane.
__global__ __launch_bounds__(256) void agg_kernel(float* __restrict__ out) {
    __shared__ float ebuf[8][MAXD];
    __shared__ float nbuf[8][MAXD];
    const int w = threadIdx.x >> 5;
    int i = (blockIdx.x * blockDim.x + threadIdx.x) >> 5;
    int lane = threadIdx.x & 31;
    if (i >= N_CELLS) return;
    int start = g_rowstart[i];
    int d = g_cnt[i];
    int end = start + d;
    float si = g_ssrc[i];

    // pass 1: e + nv into smem, fp64 rs
    double rsd = 0.0;
    for (int j = start + lane; j < end; j += 32) {
        int2 p = g_pairs[j];
        float z = si + g_sdst[p.x];
        float e = z >= 0.f ? z : 0.2f * z;
        int t = j - start;
        if (t < MAXD) {
            ebuf[w][t] = e;
            nbuf[w][t] = __int_as_float(p.y);
        }
        rsd += (double)e;
    }
#pragma unroll
    for (int off = 16; off > 0; off >>= 1)
        rsd += __shfl_xor_sync(0xffffffffu, rsd, off);
    float rsf = (float)rsd;
    __syncwarp();

    // pass 1b: lane-parallel coefficients (divisions /32)
    int dc = d > MAXD ? MAXD : d;
    for (int t = lane; t < dc; t += 32) {
        float att = ebuf[w][t] / rsf;
        ebuf[w][t] = nbuf[w][t] * att;
    }
    __syncwarp();

    // pass 2: numerator; lane owns 4 output cols; fp16 m gathers (8B/lane/edge)
    float4 acc = make_float4(0.f, 0.f, 0.f, 0.f);
    const uint2* __restrict__ MH = (const uint2*)g_mh;
#pragma unroll 2
    for (int t = 0; t < d; t++) {
        int2 p = g_pairs[start + t];
        float tt;
        if (t < MAXD) {
            tt = ebuf[w][t];
        } else {            // degree > 128: recompute (identical op order)
            float z = si + g_sdst[p.x];
            float e = z >= 0.f ? z : 0.2f * z;
            tt = __int_as_float(p.y) * (e / rsf);
        }
        uint2 hv = __ldg(&MH[(size_t)p.x * 32 + lane]);
        __half2 h0 = *(__half2*)&hv.x;
        __half2 h1 = *(__half2*)&hv.y;
        float2 f0 = __half22float2(h0);
        float2 f1 = __half22float2(h1);
        acc.x = fmaf(tt, f0.x, acc.x);
        acc.y = fmaf(tt, f0.y, acc.y);
        acc.z = fmaf(tt, f1.x, acc.z);
        acc.w = fmaf(tt, f1.y, acc.w);
    }
    *((float4*)(out + (size_t)i * D_OUT) + lane) = acc;
}

// ================= launch (fork/join: CSR build overlaps GEMM) =================
struct HbsRes {
    cudaStream_t s2;
    cudaEvent_t evFork, evJoin;
    HbsRes() {
        cudaStreamCreateWithFlags(&s2, cudaStreamNonBlocking);
        cudaEventCreateWithFlags(&evFork, cudaEventDisableTiming);
        cudaEventCreateWithFlags(&evJoin, cudaEventDisableTiming);
    }
};

extern "C" void kernel_launch(void* const* d_in, const int* in_sizes, int n_in,
                              void* d_out, int out_size) {
    static HbsRes res;

    const float* x      = (const float*)d_in[0];
    const float* W      = (const float*)d_in[1];
    const float* a      = (const float*)d_in[2];
    const float* n_vals = (const float*)d_in[3];
    const int*   n_src  = (const int*)d_in[4];
    const int*   n_dst  = (const int*)d_in[5];
    float* out = (float*)d_out;

    cudaEventRecord(res.evFork, 0);
    cudaStreamWaitEvent(res.s2, res.evFork, 0);

    zero_kernel<<<(N_CELLS + 255) / 256, 256, 0, res.s2>>>();
    hist_kernel<<<(N_EDGES / 4 + 255) / 256, 256, 0, res.s2>>>(n_src);
    alloc_kernel<<<(N_CELLS + 255) / 256, 256, 0, res.s2>>>();
    scatter_kernel<<<(N_EDGES / 4 + 255) / 256, 256, 0, res.s2>>>(n_src, n_dst, n_vals);
    cudaEventRecord(res.evJoin, res.s2);

    const int gemm_blocks = (N_CELLS + BM - 1) / BM;            // 391
    gemm_kernel<<<gemm_blocks, 256>>>(x, W);

    const int warp_blocks = (N_CELLS * 32 + 255) / 256;         // 6250
    score_kernel<<<warp_blocks, 256>>>(a);

    cudaStreamWaitEvent(0, res.evJoin, 0);
    agg_kernel<<<warp_blocks, 256>>>(out);
}

// round 17
// speedup vs baseline: 1.5793x; 1.0526x over previous
#include <cuda_runtime.h>
#include <cuda_fp16.h>

#define N_CELLS 50000
#define N_EDGES 1600000
#define D_IN 256
#define D_OUT 128
#define MAXD 128

// ---- scratch (device globals; no allocation allowed) ----
__device__ float  g_m[N_CELLS * D_OUT];     // x @ W fp32 (frozen numerics; feeds scores)
__device__ __half g_mh[N_CELLS * D_OUT];    // fp16 copy (feeds agg numerator)
__device__ float  g_ssrc[N_CELLS];
__device__ float  g_sdst[N_CELLS];
__device__ int    g_cnt[N_CELLS];
__device__ int    g_rowstart[N_CELLS];
__device__ int    g_fill[N_CELLS];
__device__ int    g_total;
__device__ int2   g_pairs[N_EDGES];         // (dst, float_bits(n_val)) grouped by src

// ---- packed f32x2 helpers (FFMA2: each half IEEE fp32 RN, bit == scalar fmaf) ----
__device__ __forceinline__ unsigned long long pk2(float lo, float hi) {
    unsigned long long r;
    asm("mov.b64 %0, {%1, %2};" : "=l"(r) : "f"(lo), "f"(hi));
    return r;
}
__device__ __forceinline__ void upk2(unsigned long long v, float& lo, float& hi) {
    asm("mov.b64 {%0, %1}, %2;" : "=f"(lo), "=f"(hi) : "l"(v));
}
__device__ __forceinline__ unsigned long long ffma2(unsigned long long a,
                                                    unsigned long long b,
                                                    unsigned long long c) {
    unsigned long long d;
    asm("fma.rn.f32x2 %0, %1, %2, %3;" : "=l"(d) : "l"(a), "l"(b), "l"(c));
    return d;
}

// ================= GEMM: g_m = x @ W (software-pipelined, FFMA2, frozen k-order) =================
#define BM 128
#define BN 128
#define BK 16

__global__ __launch_bounds__(256) void gemm_kernel(const float* __restrict__ x,
                                                   const float* __restrict__ W) {
    __shared__ float As[BK][BM + 4];
    __shared__ float Bs[BK][BN];
    const int tid = threadIdx.x;
    const int blockRow = blockIdx.x * BM;
    const int tx = tid & 15;
    const int ty = tid >> 4;

    unsigned long long acc2[8][4];
#pragma unroll
    for (int r = 0; r < 8; r++)
#pragma unroll
        for (int c = 0; c < 4; c++) acc2[r][c] = 0ull;

    const int rowA = tid >> 2;          // 0..63
    const int colA = (tid & 3) << 2;    // 0,4,8,12
    const int rowB = tid >> 5;          // 0..7
    const int colB = (tid & 31) << 2;   // 0..124

    const int grA0 = blockRow + rowA;
    const int grA1 = blockRow + rowA + 64;
    const bool okA0 = grA0 < N_CELLS;
    const bool okA1 = grA1 < N_CELLS;
    const float* pA0 = x + (size_t)(okA0 ? grA0 : 0) * D_IN + colA;
    const float* pA1 = x + (size_t)(okA1 ? grA1 : 0) * D_IN + colA;
    const float* pB0 = W + (size_t)rowB * D_OUT + colB;
    const float* pB1 = W + (size_t)(rowB + 8) * D_OUT + colB;

    // prologue: tile kk=0 into smem
    {
        float4 a0 = okA0 ? *(const float4*)pA0 : make_float4(0.f, 0.f, 0.f, 0.f);
        float4 a1 = okA1 ? *(const float4*)pA1 : make_float4(0.f, 0.f, 0.f, 0.f);
        float4 b0 = *(const float4*)pB0;
        float4 b1 = *(const float4*)pB1;
        As[colA + 0][rowA] = a0.x; As[colA + 1][rowA] = a0.y;
        As[colA + 2][rowA] = a0.z; As[colA + 3][rowA] = a0.w;
        As[colA + 0][rowA + 64] = a1.x; As[colA + 1][rowA + 64] = a1.y;
        As[colA + 2][rowA + 64] = a1.z; As[colA + 3][rowA + 64] = a1.w;
        *(float4*)(&Bs[rowB][colB]) = b0;
        *(float4*)(&Bs[rowB + 8][colB]) = b1;
    }
    __syncthreads();

    for (int kk = 0; kk < D_IN; kk += BK) {
        // prefetch next tile into registers
        float4 na0, na1, nb0, nb1;
        const bool more = (kk + BK) < D_IN;
        if (more) {
            na0 = okA0 ? *(const float4*)(pA0 + kk + BK) : make_float4(0.f, 0.f, 0.f, 0.f);
            na1 = okA1 ? *(const float4*)(pA1 + kk + BK) : make_float4(0.f, 0.f, 0.f, 0.f);
            nb0 = *(const float4*)(pB0 + (size_t)(kk + BK) * D_OUT);
            nb1 = *(const float4*)(pB1 + (size_t)(kk + BK) * D_OUT);
        }
#pragma unroll
        for (int k = 0; k < BK; k++) {
            float4 a0 = *(const float4*)(&As[k][ty * 8]);
            float4 a1 = *(const float4*)(&As[k][ty * 8 + 4]);
            float4 b0 = *(const float4*)(&Bs[k][tx * 8]);
            float4 b1 = *(const float4*)(&Bs[k][tx * 8 + 4]);
            unsigned long long nn[4] = {pk2(b0.x, b0.y), pk2(b0.z, b0.w),
                                        pk2(b1.x, b1.y), pk2(b1.z, b1.w)};
            float mA[8] = {a0.x, a0.y, a0.z, a0.w, a1.x, a1.y, a1.z, a1.w};
#pragma unroll
            for (int r = 0; r < 8; r++) {
                unsigned long long md = pk2(mA[r], mA[r]);
#pragma unroll
                for (int c = 0; c < 4; c++)
                    acc2[r][c] = ffma2(md, nn[c], acc2[r][c]);
            }
        }
        __syncthreads();
        if (more) {
            As[colA + 0][rowA] = na0.x; As[colA + 1][rowA] = na0.y;
            As[colA + 2][rowA] = na0.z; As[colA + 3][rowA] = na0.w;
            As[colA + 0][rowA + 64] = na1.x; As[colA + 1][rowA + 64] = na1.y;
            As[colA + 2][rowA + 64] = na1.z; As[colA + 3][rowA + 64] = na1.w;
            *(float4*)(&Bs[rowB][colB]) = nb0;
            *(float4*)(&Bs[rowB + 8][colB]) = nb1;
            __syncthreads();
        }
    }

#pragma unroll
    for (int r = 0; r < 8; r++) {
        int gr = blockRow + ty * 8 + r;
        if (gr < N_CELLS) {
            float f[8];
            upk2(acc2[r][0], f[0], f[1]);
            upk2(acc2[r][1], f[2], f[3]);
            upk2(acc2[r][2], f[4], f[5]);
            upk2(acc2[r][3], f[6], f[7]);
            float* dst = g_m + (size_t)gr * D_OUT + tx * 8;
            *(float4*)dst = make_float4(f[0], f[1], f[2], f[3]);
            *(float4*)(dst + 4) = make_float4(f[4], f[5], f[6], f[7]);
            __half2 h0 = __floats2half2_rn(f[0], f[1]);
            __half2 h1 = __floats2half2_rn(f[2], f[3]);
            __half2 h2 = __floats2half2_rn(f[4], f[5]);
            __half2 h3 = __floats2half2_rn(f[6], f[7]);
            uint4 hv;
            hv.x = *(unsigned int*)&h0;
            hv.y = *(unsigned int*)&h1;
            hv.z = *(unsigned int*)&h2;
            hv.w = *(unsigned int*)&h3;
            *(uint4*)(g_mh + (size_t)gr * D_OUT + tx * 8) = hv;
        }
    }
}

// ================= scores: cublas-gemv emulation (FROZEN numerics) =================
__global__ __launch_bounds__(256) void score_kernel(const float* __restrict__ a) {
    __shared__ float sa[2 * D_OUT];
    for (int j = threadIdx.x; j < 2 * D_OUT; j += blockDim.x) sa[j] = a[j];
    __syncthreads();
    int row = (blockIdx.x * blockDim.x + threadIdx.x) >> 5;
    int l = threadIdx.x & 31;
    if (row >= N_CELLS) return;
    const float* __restrict__ mr = g_m + (size_t)row * D_OUT;

    float m0 = __ldg(mr + l);
    float m1 = __ldg(mr + l + 32);
    float m2 = __ldg(mr + l + 64);
    float m3 = __ldg(mr + l + 96);

    float ss = fmaf(m0, sa[l], 0.f);
    ss = fmaf(m1, sa[l + 32], ss);
    ss = fmaf(m2, sa[l + 64], ss);
    ss = fmaf(m3, sa[l + 96], ss);

    float sd = fmaf(m0, sa[D_OUT + l], 0.f);
    sd = fmaf(m1, sa[D_OUT + l + 32], sd);
    sd = fmaf(m2, sa[D_OUT + l + 64], sd);
    sd = fmaf(m3, sa[D_OUT + l + 96], sd);

#pragma unroll
    for (int off = 16; off > 0; off >>= 1) {
        ss += __shfl_down_sync(0xffffffffu, ss, off);
        sd += __shfl_down_sync(0xffffffffu, sd, off);
    }
    if (l == 0) {
        g_ssrc[row] = ss;
        g_sdst[row] = sd;
    }
}

// ================= CSR build (scan-free, 4 edges/thread) =================
__global__ void zero_kernel() {
    int i = blockIdx.x * blockDim.x + threadIdx.x;
    if (i < N_CELLS) g_cnt[i] = 0;
    if (i == 0) g_total = 0;
}

__global__ void hist_kernel(const int* __restrict__ n_src) {
    int e = (blockIdx.x * blockDim.x + threadIdx.x) * 4;
    if (e < N_EDGES) {
        int4 s = *(const int4*)(n_src + e);
        atomicAdd(&g_cnt[s.x], 1);
        atomicAdd(&g_cnt[s.y], 1);
        atomicAdd(&g_cnt[s.z], 1);
        atomicAdd(&g_cnt[s.w], 1);
    }
}

__global__ __launch_bounds__(256) void alloc_kernel() {
    int i = blockIdx.x * blockDim.x + threadIdx.x;
    int lane = threadIdx.x & 31;
    int cnt = (i < N_CELLS) ? g_cnt[i] : 0;
    int xv = cnt;
#pragma unroll
    for (int off = 1; off < 32; off <<= 1) {
        int y = __shfl_up_sync(0xffffffffu, xv, off);
        if (lane >= off) xv += y;
    }
    int excl = xv - cnt;
    int wtotal = __shfl_sync(0xffffffffu, xv, 31);
    int base = 0;
    if (lane == 0) base = atomicAdd(&g_total, wtotal);
    base = __shfl_sync(0xffffffffu, base, 0);
    if (i < N_CELLS) {
        int s = base + excl;
        g_rowstart[i] = s;
        g_fill[i] = s;
    }
}

__global__ void scatter_kernel(const int* __restrict__ n_src,
                               const int* __restrict__ n_dst,
                               const float* __restrict__ n_vals) {
    int e = (blockIdx.x * blockDim.x + threadIdx.x) * 4;
    if (e < N_EDGES) {
        int4 s = *(const int4*)(n_src + e);
        int4 d = *(const int4*)(n_dst + e);
        float4 v = *(const float4*)(n_vals + e);
        int p0 = atomicAdd(&g_fill[s.x], 1);
        int p1 = atomicAdd(&g_fill[s.y], 1);
        int p2 = atomicAdd(&g_fill[s.z], 1);
        int p3 = atomicAdd(&g_fill[s.w], 1);
        g_pairs[p0] = make_int2(d.x, __float_as_int(v.x));
        g_pairs[p1] = make_int2(d.y, __float_as_int(v.y));
        g_pairs[p2] = make_int2(d.z, __float_as_int(v.z));
        g_pairs[p3] = make_int2(d.w, __float_as_int(v.w));
    }
}

// ================= aggregation: one warp per cell =================
// pass1: e -> ebuf, nv -> nbuf, dst -> dbuf (smem), fp64 rs.
// pass1b: in-place coefficient ebuf[t] = nbuf[t]*(ebuf[t]/rsf)  (bit-identical).
// pass2: addresses from smem -> 4 INDEPENDENT gathers in flight (MLP 4).
__global__ __launch_bounds__(256) void agg_kernel(float* __restrict__ out) {
    __shared__ float ebuf[8][MAXD];
    __shared__ float nbuf[8][MAXD];
    __shared__ int   dbuf[8][MAXD];
    const int w = threadIdx.x >> 5;
    int i = (blockIdx.x * blockDim.x + threadIdx.x) >> 5;
    int lane = threadIdx.x & 31;
    if (i >= N_CELLS) return;
    int start = g_rowstart[i];
    int d = g_cnt[i];
    int end = start + d;
    float si = g_ssrc[i];

    // pass 1: e + nv + dst into smem, fp64 rs
    double rsd = 0.0;
    for (int j = start + lane; j < end; j += 32) {
        int2 p = g_pairs[j];
        float z = si + g_sdst[p.x];
        float e = z >= 0.f ? z : 0.2f * z;
        int t = j - start;
        if (t < MAXD) {
            ebuf[w][t] = e;
            nbuf[w][t] = __int_as_float(p.y);
            dbuf[w][t] = p.x;
        }
        rsd += (double)e;
    }
#pragma unroll
    for (int off = 16; off > 0; off >>= 1)
        rsd += __shfl_xor_sync(0xffffffffu, rsd, off);
    float rsf = (float)rsd;
    __syncwarp();

    // pass 1b: lane-parallel coefficients (divisions /32)
    int dc = d > MAXD ? MAXD : d;
    for (int t = lane; t < dc; t += 32) {
        float att = ebuf[w][t] / rsf;
        ebuf[w][t] = nbuf[w][t] * att;
    }
    __syncwarp();

    // pass 2: batched independent gathers (unroll 4), t ascending (same sum order)
    float4 acc = make_float4(0.f, 0.f, 0.f, 0.f);
    const uint2* __restrict__ MH = (const uint2*)g_mh;
    int t = 0;
    for (; t + 4 <= dc; t += 4) {
        int d0 = dbuf[w][t];
        int d1 = dbuf[w][t + 1];
        int d2 = dbuf[w][t + 2];
        int d3 = dbuf[w][t + 3];
        uint2 v0 = __ldg(&MH[(size_t)d0 * 32 + lane]);
        uint2 v1 = __ldg(&MH[(size_t)d1 * 32 + lane]);
        uint2 v2 = __ldg(&MH[(size_t)d2 * 32 + lane]);
        uint2 v3 = __ldg(&MH[(size_t)d3 * 32 + lane]);
        float c0 = ebuf[w][t];
        float c1 = ebuf[w][t + 1];
        float c2 = ebuf[w][t + 2];
        float c3 = ebuf[w][t + 3];
        float2 f;
        f = __half22float2(*(__half2*)&v0.x);
        acc.x = fmaf(c0, f.x, acc.x); acc.y = fmaf(c0, f.y, acc.y);
        f = __half22float2(*(__half2*)&v0.y);
        acc.z = fmaf(c0, f.x, acc.z); acc.w = fmaf(c0, f.y, acc.w);
        f = __half22float2(*(__half2*)&v1.x);
        acc.x = fmaf(c1, f.x, acc.x); acc.y = fmaf(c1, f.y, acc.y);
        f = __half22float2(*(__half2*)&v1.y);
        acc.z = fmaf(c1, f.x, acc.z); acc.w = fmaf(c1, f.y, acc.w);
        f = __half22float2(*(__half2*)&v2.x);
        acc.x = fmaf(c2, f.x, acc.x); acc.y = fmaf(c2, f.y, acc.y);
        f = __half22float2(*(__half2*)&v2.y);
        acc.z = fmaf(c2, f.x, acc.z); acc.w = fmaf(c2, f.y, acc.w);
        f = __half22float2(*(__half2*)&v3.x);
        acc.x = fmaf(c3, f.x, acc.x); acc.y = fmaf(c3, f.y, acc.y);
        f = __half22float2(*(__half2*)&v3.y);
        acc.z = fmaf(c3, f.x, acc.z); acc.w = fmaf(c3, f.y, acc.w);
    }
    for (; t < dc; t++) {
        int dd = dbuf[w][t];
        float c = ebuf[w][t];
        uint2 hv = __ldg(&MH[(size_t)dd * 32 + lane]);
        float2 f0 = __half22float2(*(__half2*)&hv.x);
        float2 f1 = __half22float2(*(__half2*)&hv.y);
        acc.x = fmaf(c, f0.x, acc.x);
        acc.y = fmaf(c, f0.y, acc.y);
        acc.z = fmaf(c, f1.x, acc.z);
        acc.w = fmaf(c, f1.y, acc.w);
    }
    // degree > MAXD tail (recompute; identical op order)
    for (int tt = MAXD; tt < d; tt++) {
        int2 p = g_pairs[start + tt];
        float z = si + g_sdst[p.x];
        float e = z >= 0.f ? z : 0.2f * z;
        float c = __int_as_float(p.y) * (e / rsf);
        uint2 hv = __ldg(&MH[(size_t)p.x * 32 + lane]);
        float2 f0 = __half22float2(*(__half2*)&hv.x);
        float2 f1 = __half22float2(*(__half2*)&hv.y);
        acc.x = fmaf(c, f0.x, acc.x);
        acc.y = fmaf(c, f0.y, acc.y);
        acc.z = fmaf(c, f1.x, acc.z);
        acc.w = fmaf(c, f1.y, acc.w);
    }
    *((float4*)(out + (size_t)i * D_OUT) + lane) = acc;
}

// ================= launch (fork/join: CSR build overlaps GEMM) =================
struct HbsRes {
    cudaStream_t s2;
    cudaEvent_t evFork, evJoin;
    HbsRes() {
        cudaStreamCreateWithFlags(&s2, cudaStreamNonBlocking);
        cudaEventCreateWithFlags(&evFork, cudaEventDisableTiming);
        cudaEventCreateWithFlags(&evJoin, cudaEventDisableTiming);
    }
};

extern "C" void kernel_launch(void* const* d_in, const int* in_sizes, int n_in,
                              void* d_out, int out_size) {
    static HbsRes res;

    const float* x      = (const float*)d_in[0];
    const float* W      = (const float*)d_in[1];
    const float* a      = (const float*)d_in[2];
    const float* n_vals = (const float*)d_in[3];
    const int*   n_src  = (const int*)d_in[4];
    const int*   n_dst  = (const int*)d_in[5];
    float* out = (float*)d_out;

    cudaEventRecord(res.evFork, 0);
    cudaStreamWaitEvent(res.s2, res.evFork, 0);

    zero_kernel<<<(N_CELLS + 255) / 256, 256, 0, res.s2>>>();
    hist_kernel<<<(N_EDGES / 4 + 255) / 256, 256, 0, res.s2>>>(n_src);
    alloc_kernel<<<(N_CELLS + 255) / 256, 256, 0, res.s2>>>();
    scatter_kernel<<<(N_EDGES / 4 + 255) / 256, 256, 0, res.s2>>>(n_src, n_dst, n_vals);
    cudaEventRecord(res.evJoin, res.s2);

    const int gemm_blocks = (N_CELLS + BM - 1) / BM;            // 391
    gemm_kernel<<<gemm_blocks, 256>>>(x, W);

    const int warp_blocks = (N_CELLS * 32 + 255) / 256;         // 6250
    score_kernel<<<warp_blocks, 256>>>(a);

    cudaStreamWaitEvent(0, res.evJoin, 0);
    agg_kernel<<<warp_blocks, 256>>>(out);
}